// round 2
// baseline (speedup 1.0000x reference)
#include <cuda_runtime.h>
#include <math.h>

// ---------------- problem constants (fixed shapes) ----------------
#define B_      2
#define N_      6
#define CAMS    (B_ * N_)          // 12
#define CAM_C   256
#define OUT_C   64
#define D_BINS  59
#define M_FEAT  (D_BINS + OUT_C)   // 123
#define FH      16
#define FW      44
#define HW      (FH * FW)          // 704
#define NX      128
#define NY      128
#define NCELL   (NX * NY)          // 16384 (NZ = 1)

// GEMM tiling
#define BM 128          // padded from 123
#define BN 64           // pixels per block
#define BK 32
#define NCHUNK (CAM_C / BK)   // 8
#define NTHREADS 256

#define WS_STRIDE 128   // Ws row (floats)
#define XS_STRIDE 68    // Xs row (floats)
#define DS_STRIDE 61    // depthS row per pixel (odd -> conflict free)
#define CS_STRIDE 68    // ctxS row per pixel

typedef unsigned long long ull;

// scratch BEV accumulator, channel-contiguous: (B, cell, OUT_C).
// Zero-initialized at module load; transpose kernel re-zeroes after reading,
// so it is always zero at kernel_launch entry (graph replays included).
__device__ float g_scratch[B_ * NCELL * OUT_C];   // 8 MB
// transposed weights: Wt[k][m], m padded to 128 with zeros
__device__ float g_Wt[CAM_C * BM];

// ---------------- cp.async helpers ----------------
__device__ __forceinline__ void cp_async16(void* sptr, const void* gptr) {
    unsigned sa = (unsigned)__cvta_generic_to_shared(sptr);
    asm volatile("cp.async.cg.shared.global [%0], [%1], 16;" :: "r"(sa), "l"(gptr));
}
#define CP_COMMIT() asm volatile("cp.async.commit_group;")
#define CP_WAIT1()  asm volatile("cp.async.wait_group 1;" ::: "memory")

// ---------------- weight transpose prep ----------------
__global__ void prep_wt_kernel(const float* __restrict__ depth_w) {
    int idx = blockIdx.x * blockDim.x + threadIdx.x;   // 0..32767
    int m = idx >> 8;          // 0..127
    int k = idx & 255;         // coalesced read along k
    g_Wt[k * BM + m] = (m < M_FEAT) ? depth_w[m * CAM_C + k] : 0.f;
}

// ---------------- fused GEMM + softmax + scatter ----------------
__global__ __launch_bounds__(NTHREADS, 1)
void lss_fused_kernel(const float* __restrict__ x,
                      const float* __restrict__ rots,
                      const float* __restrict__ trans,
                      const float* __restrict__ intrins,
                      const float* __restrict__ depth_b)
{
    // phase 1: Ws double buffer (2*32*128) + Xs (32*68)  = 10368 floats = 41472 B
    // phase 2 alias: depthS (64*61=3904) + ctxS (64*68=4352) = 8256 floats
    __shared__ __align__(16) float smem[2 * BK * WS_STRIDE + BK * XS_STRIDE];
    __shared__ float comb[9];
    __shared__ float tr[3];

    float* Ws0 = smem;
    float* Ws1 = smem + BK * WS_STRIDE;
    float* Xs  = smem + 2 * BK * WS_STRIDE;

    const int cam = blockIdx.y;           // 0..11
    const int b   = cam / N_;
    const int p0  = blockIdx.x * BN;      // pixel tile start
    const int tid = threadIdx.x;
    const int tm  = tid >> 4;             // 0..15 -> 8 M-rows (4 pairs)
    const int tn  = tid & 15;             // 0..15 -> 4 pixels

    // --- geometry setup: comb = rots @ inv(K) (thread 0) ---
    if (tid == 0) {
        const float* R = rots    + cam * 9;
        const float* K = intrins + cam * 9;
        float a = K[0], bb = K[1], c = K[2];
        float d = K[3], e  = K[4], f = K[5];
        float g = K[6], h  = K[7], i = K[8];
        float A  = e * i - f * h;
        float Bv = -(d * i - f * g);
        float Cv = d * h - e * g;
        float id = 1.0f / (a * A + bb * Bv + c * Cv);
        float inv[9];
        inv[0] = A * id;  inv[1] = (c * h - bb * i) * id; inv[2] = (bb * f - c * e) * id;
        inv[3] = Bv * id; inv[4] = (a * i - c * g) * id;  inv[5] = (c * d - a * f) * id;
        inv[6] = Cv * id; inv[7] = (bb * g - a * h) * id; inv[8] = (a * e - bb * d) * id;
        #pragma unroll
        for (int r = 0; r < 3; r++)
            #pragma unroll
            for (int col = 0; col < 3; col++)
                comb[r * 3 + col] = R[r * 3 + 0] * inv[0 + col]
                                  + R[r * 3 + 1] * inv[3 + col]
                                  + R[r * 3 + 2] * inv[6 + col];
        tr[0] = trans[cam * 3 + 0];
        tr[1] = trans[cam * 3 + 1];
        tr[2] = trans[cam * 3 + 2];
    }

    const float* xcam = x + (size_t)cam * CAM_C * HW;

    // X register-prefetch addressing: thread covers two float4 of the chunk
    const int q0  = tid * 2;
    const int kkA = q0 >> 4,       sA = q0 & 15;        // 16 float4 per kk-row
    const int q1  = q0 + 1;
    const int kkB = q1 >> 4,       sB = q1 & 15;

    // --- prologue: X chunk 0 -> regs -> smem; cp.async W chunks 0,1 ---
    float4 xrA = *(const float4*)(xcam + (size_t)kkA * HW + p0 + sA * 4);
    float4 xrB = *(const float4*)(xcam + (size_t)kkB * HW + p0 + sB * 4);
    *(float4*)&Xs[kkA * XS_STRIDE + sA * 4] = xrA;
    *(float4*)&Xs[kkB * XS_STRIDE + sB * 4] = xrB;

    #pragma unroll
    for (int o = 0; o < 4; o++) {
        int q = o * NTHREADS + tid;             // 0..1023
        int kk = q >> 5, seg = q & 31;          // 32 x 16B per kk-row
        cp_async16(Ws0 + kk * WS_STRIDE + seg * 4, g_Wt + (0 * BK + kk) * BM + seg * 4);
    }
    CP_COMMIT();
    #pragma unroll
    for (int o = 0; o < 4; o++) {
        int q = o * NTHREADS + tid;
        int kk = q >> 5, seg = q & 31;
        cp_async16(Ws1 + kk * WS_STRIDE + seg * 4, g_Wt + (1 * BK + kk) * BM + seg * 4);
    }
    CP_COMMIT();
    __syncthreads();   // Xs chunk0 visible

    // --- mainloop: FFMA2 GEMM, M-pairs x 4 pixels per thread ---
    ull acc[4][4];
    #pragma unroll
    for (int i4 = 0; i4 < 4; i4++)
        #pragma unroll
        for (int j = 0; j < 4; j++) acc[i4][j] = 0ull;

    for (int c = 0; c < NCHUNK; c++) {
        // prefetch next X chunk into registers (in-flight across compute)
        if (c + 1 < NCHUNK) {
            const float* xc = xcam + (size_t)(c + 1) * BK * HW + p0;
            xrA = *(const float4*)(xc + (size_t)kkA * HW + sA * 4);
            xrB = *(const float4*)(xc + (size_t)kkB * HW + sB * 4);
        }
        CP_WAIT1();        // W buffer for chunk c arrived
        __syncthreads();   // publish W smem (+ Xs stores from prev iter)

        const float* Wsb = (c & 1) ? Ws1 : Ws0;
        #pragma unroll 4
        for (int kk = 0; kk < BK; kk++) {
            ull wp[4];
            #pragma unroll
            for (int i4 = 0; i4 < 4; i4++)
                wp[i4] = *(const ull*)&Wsb[kk * WS_STRIDE + tm * 8 + 2 * i4];
            ull xd[4];
            #pragma unroll
            for (int j = 0; j < 4; j++) {
                float xv = Xs[kk * XS_STRIDE + tn * 4 + j];
                asm("mov.b64 %0, {%1, %1};" : "=l"(xd[j]) : "f"(xv));
            }
            #pragma unroll
            for (int i4 = 0; i4 < 4; i4++)
                #pragma unroll
                for (int j = 0; j < 4; j++)
                    asm("fma.rn.f32x2 %0, %1, %2, %0;"
                        : "+l"(acc[i4][j]) : "l"(wp[i4]), "l"(xd[j]));
        }
        __syncthreads();   // everyone done reading Xs / Ws(c)

        if (c + 1 < NCHUNK) {
            *(float4*)&Xs[kkA * XS_STRIDE + sA * 4] = xrA;
            *(float4*)&Xs[kkB * XS_STRIDE + sB * 4] = xrB;
            if (c + 2 < NCHUNK) {
                float* Wnext = (c & 1) ? Ws1 : Ws0;   // buffer just freed
                #pragma unroll
                for (int o = 0; o < 4; o++) {
                    int q = o * NTHREADS + tid;
                    int kk = q >> 5, seg = q & 31;
                    cp_async16(Wnext + kk * WS_STRIDE + seg * 4,
                               g_Wt + ((c + 2) * BK + kk) * BM + seg * 4);
                }
                CP_COMMIT();
            }
        }
    }

    // --- phase 2: unpack accs (+bias) into depthS / ctxS ---
    float* depthS = smem;                     // [pix][61]
    float* ctxS   = smem + BN * DS_STRIDE;    // [pix][68]

    #pragma unroll
    for (int i4 = 0; i4 < 4; i4++) {
        int m0 = tm * 8 + 2 * i4;
        float b0 = (m0     < M_FEAT) ? depth_b[m0]     : 0.f;
        float b1 = (m0 + 1 < M_FEAT) ? depth_b[m0 + 1] : 0.f;
        #pragma unroll
        for (int j = 0; j < 4; j++) {
            float lo, hi;
            asm("mov.b64 {%0, %1}, %2;" : "=f"(lo), "=f"(hi) : "l"(acc[i4][j]));
            int pix = tn * 4 + j;
            float v0 = lo + b0, v1 = hi + b1;
            if (m0 < D_BINS)       depthS[pix * DS_STRIDE + m0] = v0;
            else if (m0 < M_FEAT)  ctxS[pix * CS_STRIDE + (m0 - D_BINS)] = v0;
            int m1 = m0 + 1;
            if (m1 < D_BINS)       depthS[pix * DS_STRIDE + m1] = v1;
            else if (m1 < M_FEAT)  ctxS[pix * CS_STRIDE + (m1 - D_BINS)] = v1;
        }
    }
    __syncthreads();

    // --- softmax over depth bins, one thread per pixel ---
    if (tid < BN) {
        float* row = depthS + tid * DS_STRIDE;
        float mx = -1e30f;
        #pragma unroll 4
        for (int d = 0; d < D_BINS; d++) mx = fmaxf(mx, row[d]);
        float s = 0.f;
        #pragma unroll 4
        for (int d = 0; d < D_BINS; d++) {
            float e = __expf(row[d] - mx);
            row[d] = e;
            s += e;
        }
        float invs = 1.0f / s;
        #pragma unroll 4
        for (int d = 0; d < D_BINS; d++) row[d] *= invs;
    }
    __syncthreads();

    // --- scatter: thread = (pixel, depth-chunk), run-merged red.v4 ---
    const float c00 = comb[0], c01 = comb[1], c02 = comb[2];
    const float c10 = comb[3], c11 = comb[4], c12 = comb[5];
    const float c20 = comb[6], c21 = comb[7], c22 = comb[8];
    const float t0 = tr[0], t1 = tr[1], t2 = tr[2];
    const float xstep = 703.0f / 43.0f;
    const float ystep = 255.0f / 15.0f;

    {
        const int pix   = tid >> 2;          // 0..63
        const int chunk = tid & 3;           // 0..3
        const int d0    = chunk * 15;
        const int dend  = (chunk == 3) ? D_BINS : d0 + 15;

        const int hw = p0 + pix;
        const int h  = hw / FW;
        const int w  = hw - h * FW;
        const float xim = (float)w * xstep;
        const float yim = (float)h * ystep;

        // ray direction and start point (g = t + ds * r, ds = 1 + dbin)
        const float rx = c00 * xim + c01 * yim + c02;
        const float ry = c10 * xim + c11 * yim + c12;
        const float rz = c20 * xim + c21 * yim + c22;
        float gx = t0 + (float)(1 + d0) * rx;
        float gy = t1 + (float)(1 + d0) * ry;
        float gz = t2 + (float)(1 + d0) * rz;

        const float* ctx = ctxS + pix * CS_STRIDE;
        const float* drow = depthS + pix * DS_STRIDE;
        float* base = g_scratch + (size_t)b * NCELL * OUT_C;

        int prev = -1;
        float wacc = 0.f;
        for (int d = d0; d < dend; d++) {
            int cx = (int)floorf((gx + 51.2f) / 0.8f);
            int cy = (int)floorf((gy + 51.2f) / 0.8f);
            int cz = (int)floorf((gz + 10.0f) / 20.0f);
            bool ok = ((unsigned)cx < (unsigned)NX) && ((unsigned)cy < (unsigned)NY) && (cz == 0);
            int cell = ok ? (cy * NX + cx) : -1;
            if (cell != prev) {
                if (prev >= 0) {
                    float* dst = base + (size_t)prev * OUT_C;
                    #pragma unroll
                    for (int c4 = 0; c4 < OUT_C / 4; c4++) {
                        float4 v = *(const float4*)(ctx + c4 * 4);
                        asm volatile("red.global.add.v4.f32 [%0], {%1, %2, %3, %4};"
                                     :: "l"(dst + c4 * 4),
                                        "f"(v.x * wacc), "f"(v.y * wacc),
                                        "f"(v.z * wacc), "f"(v.w * wacc) : "memory");
                    }
                }
                prev = cell;
                wacc = 0.f;
            }
            if (ok) wacc += drow[d];
            gx += rx; gy += ry; gz += rz;
        }
        if (prev >= 0) {
            float* dst = base + (size_t)prev * OUT_C;
            #pragma unroll
            for (int c4 = 0; c4 < OUT_C / 4; c4++) {
                float4 v = *(const float4*)(ctx + c4 * 4);
                asm volatile("red.global.add.v4.f32 [%0], {%1, %2, %3, %4};"
                             :: "l"(dst + c4 * 4),
                                "f"(v.x * wacc), "f"(v.y * wacc),
                                "f"(v.z * wacc), "f"(v.w * wacc) : "memory");
            }
        }
    }
}

// -------- transpose (B, cell, C) -> (B, C, cell) + self-clean scratch --------
__global__ void transpose_bev_kernel(float* __restrict__ out)
{
    __shared__ float tile[32][33];
    int bz    = blockIdx.z;                 // batch
    int c0    = blockIdx.y * 32;            // channel tile
    int cell0 = blockIdx.x * 32;            // cell tile
    int tx = threadIdx.x, ty = threadIdx.y; // 32 x 8

    #pragma unroll
    for (int i = ty; i < 32; i += 8) {
        size_t off = ((size_t)bz * NCELL + cell0 + i) * OUT_C + c0 + tx;
        tile[i][tx] = g_scratch[off];
        g_scratch[off] = 0.f;               // restore zero for next replay
    }
    __syncthreads();
    #pragma unroll
    for (int i = ty; i < 32; i += 8)
        out[((size_t)(bz * OUT_C + c0 + i)) * NCELL + cell0 + tx] = tile[tx][i];
}

// ---------------- launch ----------------
extern "C" void kernel_launch(void* const* d_in, const int* in_sizes, int n_in,
                              void* d_out, int out_size)
{
    const float* x       = (const float*)d_in[0];
    const float* rots    = (const float*)d_in[1];
    const float* trans   = (const float*)d_in[2];
    const float* intrins = (const float*)d_in[3];
    const float* depth_w = (const float*)d_in[4];
    const float* depth_b = (const float*)d_in[5];
    float* out = (float*)d_out;

    // build transposed/padded weight matrix
    prep_wt_kernel<<<(CAM_C * BM) / NTHREADS, NTHREADS>>>(depth_w);

    // fused GEMM + softmax + scatter
    {
        dim3 grid(HW / BN, CAMS);   // (11, 12)
        lss_fused_kernel<<<grid, NTHREADS>>>(x, rots, trans, intrins, depth_b);
    }

    // transpose scratch into output layout (B, OUT_C, NY, NX), re-zero scratch
    {
        dim3 grid(NCELL / 32, OUT_C / 32, B_);   // (512, 2, 2)
        transpose_bev_kernel<<<grid, dim3(32, 8)>>>(out);
    }
    (void)in_sizes; (void)n_in; (void)out_size;
}

// round 3
// speedup vs baseline: 1.1211x; 1.1211x over previous
#include <cuda_runtime.h>
#include <math.h>

// ---------------- problem constants (fixed shapes) ----------------
#define B_      2
#define N_      6
#define CAMS    (B_ * N_)          // 12
#define CAM_C   256
#define OUT_C   64
#define D_BINS  59
#define M_FEAT  (D_BINS + OUT_C)   // 123
#define FH      16
#define FW      44
#define HW      (FH * FW)          // 704
#define NX      128
#define NY      128
#define NCELL   (NX * NY)          // 16384 (NZ = 1)

// GEMM tiling
#define BM 128          // padded from 123
#define BN 64           // pixels per block
#define BK 32
#define NCHUNK (CAM_C / BK)   // 8
#define NTHREADS 256

#define WS_STRIDE 130   // even -> aligned LDS.64; (2kk+m)%32 -> only 2-way store conflict
#define XS_STRIDE 68
#define DS_STRIDE 61    // depthS per-pixel row, odd -> conflict-free both phases
#define CS_STRIDE 68    // ctxS per-pixel row, 272B (16B multiple) -> aligned float4

typedef unsigned long long ull;

// scratch BEV accumulator, channel-contiguous: (B, cell, OUT_C).
// Zero-initialized at module load; transpose kernel re-zeroes after reading,
// so it is always zero at kernel_launch entry (graph replays included).
__device__ float g_scratch[B_ * NCELL * OUT_C];   // 8 MB

// ---------------- fused GEMM + softmax + scatter ----------------
__global__ __launch_bounds__(NTHREADS, 1)
void lss_fused_kernel(const float* __restrict__ x,
                      const float* __restrict__ rots,
                      const float* __restrict__ trans,
                      const float* __restrict__ intrins,
                      const float* __restrict__ depth_w,
                      const float* __restrict__ depth_b)
{
    // phase 1: Ws[32][130] (4160) + Xs[32][68] (2176) = 6336 floats
    // phase 2: depthS[64][61] (3904) + ctxS[64][68] (4352) = 8256 floats (33 KB)
    __shared__ __align__(16) float smem[BN * DS_STRIDE + BN * CS_STRIDE];
    __shared__ float comb[9];
    __shared__ float tr[3];

    float* Ws = smem;                       // [kk][m], stride 130
    float* Xs = smem + BK * WS_STRIDE;      // [kk][np], stride 68

    const int cam = blockIdx.y;           // 0..11
    const int b   = cam / N_;
    const int p0  = blockIdx.x * BN;      // pixel tile start
    const int tid = threadIdx.x;
    const int tm  = tid >> 4;             // 0..15 -> 8 M-rows (4 even pairs)
    const int tn  = tid & 15;             // 0..15 -> 4 pixels

    // --- geometry setup: comb = rots @ inv(K) (thread 0) ---
    if (tid == 0) {
        const float* R = rots    + cam * 9;
        const float* K = intrins + cam * 9;
        float a = K[0], bb = K[1], c = K[2];
        float d = K[3], e  = K[4], f = K[5];
        float g = K[6], h  = K[7], i = K[8];
        float A  = e * i - f * h;
        float Bv = -(d * i - f * g);
        float Cv = d * h - e * g;
        float id = 1.0f / (a * A + bb * Bv + c * Cv);
        float inv[9];
        inv[0] = A * id;  inv[1] = (c * h - bb * i) * id; inv[2] = (bb * f - c * e) * id;
        inv[3] = Bv * id; inv[4] = (a * i - c * g) * id;  inv[5] = (c * d - a * f) * id;
        inv[6] = Cv * id; inv[7] = (bb * g - a * h) * id; inv[8] = (a * e - bb * d) * id;
        #pragma unroll
        for (int r = 0; r < 3; r++)
            #pragma unroll
            for (int col = 0; col < 3; col++)
                comb[r * 3 + col] = R[r * 3 + 0] * inv[0 + col]
                                  + R[r * 3 + 1] * inv[3 + col]
                                  + R[r * 3 + 2] * inv[6 + col];
        tr[0] = trans[cam * 3 + 0];
        tr[1] = trans[cam * 3 + 1];
        tr[2] = trans[cam * 3 + 2];
    }

    // --- phase 1: feat = W @ x, FFMA2 over M-pairs ---
    ull acc[4][4];
    #pragma unroll
    for (int i4 = 0; i4 < 4; i4++)
        #pragma unroll
        for (int j = 0; j < 4; j++) acc[i4][j] = 0ull;

    const float* xcam = x + (size_t)cam * CAM_C * HW;

    for (int kc = 0; kc < CAM_C; kc += BK) {
        // load W chunk transposed: Ws[kk][m] = W[m][kc+kk] (coalesced global)
        #pragma unroll
        for (int idx = tid; idx < BM * BK; idx += NTHREADS) {
            int m  = idx >> 5;
            int kk = idx & 31;
            Ws[kk * WS_STRIDE + m] = (m < M_FEAT) ? depth_w[m * CAM_C + kc + kk] : 0.f;
        }
        // load X chunk: Xs[kk][np] = x[kc+kk][p0+np] (coalesced)
        #pragma unroll
        for (int idx = tid; idx < BK * BN; idx += NTHREADS) {
            int kk = idx >> 6;
            int np = idx & 63;
            Xs[kk * XS_STRIDE + np] = xcam[(size_t)(kc + kk) * HW + p0 + np];
        }
        __syncthreads();

        #pragma unroll 4
        for (int kk = 0; kk < BK; kk++) {
            ull wp[4];
            #pragma unroll
            for (int i4 = 0; i4 < 4; i4++)
                wp[i4] = *(const ull*)&Ws[kk * WS_STRIDE + tm * 8 + 2 * i4];
            ull xd[4];
            #pragma unroll
            for (int j = 0; j < 4; j++) {
                float xv = Xs[kk * XS_STRIDE + tn * 4 + j];
                asm("mov.b64 %0, {%1, %1};" : "=l"(xd[j]) : "f"(xv));
            }
            #pragma unroll
            for (int i4 = 0; i4 < 4; i4++)
                #pragma unroll
                for (int j = 0; j < 4; j++)
                    asm("fma.rn.f32x2 %0, %1, %2, %0;"
                        : "+l"(acc[i4][j]) : "l"(wp[i4]), "l"(xd[j]));
        }
        __syncthreads();
    }

    // --- phase 2: unpack accs (+bias) into depthS / ctxS ---
    float* depthS = smem;                     // [pix][61]
    float* ctxS   = smem + BN * DS_STRIDE;    // [pix][68]

    #pragma unroll
    for (int i4 = 0; i4 < 4; i4++) {
        int m0 = tm * 8 + 2 * i4;
        float b0 = (m0     < M_FEAT) ? depth_b[m0]     : 0.f;
        float b1 = (m0 + 1 < M_FEAT) ? depth_b[m0 + 1] : 0.f;
        #pragma unroll
        for (int j = 0; j < 4; j++) {
            float lo, hi;
            asm("mov.b64 {%0, %1}, %2;" : "=f"(lo), "=f"(hi) : "l"(acc[i4][j]));
            int pix = tn * 4 + j;
            float v0 = lo + b0, v1 = hi + b1;
            if (m0 < D_BINS)       depthS[pix * DS_STRIDE + m0] = v0;
            else if (m0 < M_FEAT)  ctxS[pix * CS_STRIDE + (m0 - D_BINS)] = v0;
            int m1 = m0 + 1;
            if (m1 < D_BINS)       depthS[pix * DS_STRIDE + m1] = v1;
            else if (m1 < M_FEAT)  ctxS[pix * CS_STRIDE + (m1 - D_BINS)] = v1;
        }
    }
    __syncthreads();

    // --- softmax over depth bins, one thread per pixel ---
    if (tid < BN) {
        float* row = depthS + tid * DS_STRIDE;
        float mx = -1e30f;
        #pragma unroll 4
        for (int d = 0; d < D_BINS; d++) mx = fmaxf(mx, row[d]);
        float s = 0.f;
        #pragma unroll 4
        for (int d = 0; d < D_BINS; d++) {
            float e = __expf(row[d] - mx);
            row[d] = e;
            s += e;
        }
        float invs = 1.0f / s;
        #pragma unroll 4
        for (int d = 0; d < D_BINS; d++) row[d] *= invs;
    }
    __syncthreads();

    // --- scatter: flat loop, 16x red.v4 per point (R1 shape) ---
    const float c00 = comb[0], c01 = comb[1], c02 = comb[2];
    const float c10 = comb[3], c11 = comb[4], c12 = comb[5];
    const float c20 = comb[6], c21 = comb[7], c22 = comb[8];
    const float t0 = tr[0], t1 = tr[1], t2 = tr[2];
    const float xstep = 703.0f / 43.0f;
    const float ystep = 255.0f / 15.0f;

    for (int idx = tid; idx < BN * D_BINS; idx += NTHREADS) {
        int pix = idx / D_BINS;
        int d   = idx - pix * D_BINS;
        int hw  = p0 + pix;
        int h   = hw / FW;
        int w   = hw - h * FW;

        float ds  = 1.0f + (float)d;
        float xim = (float)w * xstep;
        float yim = (float)h * ystep;
        float px = xim * ds, py = yim * ds, pz = ds;

        float gx = c00 * px + c01 * py + c02 * pz + t0;
        float gy = c10 * px + c11 * py + c12 * pz + t1;
        float gz = c20 * px + c21 * py + c22 * pz + t2;

        int cx = (int)floorf((gx + 51.2f) / 0.8f);
        int cy = (int)floorf((gy + 51.2f) / 0.8f);
        int cz = (int)floorf((gz + 10.0f) / 20.0f);

        if (((unsigned)cx < (unsigned)NX) && ((unsigned)cy < (unsigned)NY) && cz == 0) {
            float dwgt = depthS[pix * DS_STRIDE + d];
            float* dst = g_scratch + ((size_t)b * NCELL + (size_t)cy * NX + cx) * OUT_C;
            const float4* cv = (const float4*)(ctxS + pix * CS_STRIDE);
            #pragma unroll
            for (int c4 = 0; c4 < OUT_C / 4; c4++) {
                float4 v = cv[c4];
                asm volatile(
                    "red.global.add.v4.f32 [%0], {%1, %2, %3, %4};"
                    :: "l"(dst + c4 * 4),
                       "f"(v.x * dwgt), "f"(v.y * dwgt), "f"(v.z * dwgt), "f"(v.w * dwgt)
                    : "memory");
            }
        }
    }
}

// -------- transpose (B, cell, C) -> (B, C, cell) + self-clean scratch --------
__global__ void transpose_bev_kernel(float* __restrict__ out)
{
    __shared__ float tile[32][33];
    int bz    = blockIdx.z;                 // batch
    int c0    = blockIdx.y * 32;            // channel tile
    int cell0 = blockIdx.x * 32;            // cell tile
    int tx = threadIdx.x, ty = threadIdx.y; // 32 x 8

    #pragma unroll
    for (int i = ty; i < 32; i += 8) {
        size_t off = ((size_t)bz * NCELL + cell0 + i) * OUT_C + c0 + tx;
        tile[i][tx] = g_scratch[off];
        g_scratch[off] = 0.f;               // restore zero for next replay
    }
    __syncthreads();
    #pragma unroll
    for (int i = ty; i < 32; i += 8)
        out[((size_t)(bz * OUT_C + c0 + i)) * NCELL + cell0 + tx] = tile[tx][i];
}

// ---------------- launch ----------------
extern "C" void kernel_launch(void* const* d_in, const int* in_sizes, int n_in,
                              void* d_out, int out_size)
{
    const float* x       = (const float*)d_in[0];
    const float* rots    = (const float*)d_in[1];
    const float* trans   = (const float*)d_in[2];
    const float* intrins = (const float*)d_in[3];
    const float* depth_w = (const float*)d_in[4];
    const float* depth_b = (const float*)d_in[5];
    float* out = (float*)d_out;

    // fused GEMM + softmax + scatter: one block per (camera, 64-pixel tile)
    {
        dim3 grid(HW / BN, CAMS);   // (11, 12)
        lss_fused_kernel<<<grid, NTHREADS>>>(x, rots, trans, intrins, depth_w, depth_b);
    }

    // transpose scratch into output layout (B, OUT_C, NY, NX), re-zero scratch
    {
        dim3 grid(NCELL / 32, OUT_C / 32, B_);   // (512, 2, 2)
        transpose_bev_kernel<<<grid, dim3(32, 8)>>>(out);
    }
    (void)in_sizes; (void)n_in; (void)out_size;
}